// round 5
// baseline (speedup 1.0000x reference)
#include <cuda_runtime.h>
#include <cuda_bf16.h>
#include <cstdint>
#include <cstddef>

#define BROWS 8192
#define INDIM 8192
#define EMBD  2048

// ---------------- device scratch (static; no allocs) ----------------
__device__ float          g_Wcat[48 * INDIM];         // packed projection weights (rows 42..47 zero)
__device__ float          g_dots[4 * BROWS * 52];     // per-row partial dots over 4 j-quarters; col 48 = sum(x^2)
__device__ float          g_params[BROWS * 24];       // per row: E[16], ww[4], c[4]
__device__ __nv_bfloat16  g_branch[BROWS * EMBD];
__device__ __nv_bfloat16  g_wmodb[EMBD * EMBD];

// ---------------- prep: pack 48 projection rows ----------------
__global__ void prep_wcat(const float* __restrict__ Wr, const float* __restrict__ Ww,
                          const float* __restrict__ Wdtc, const float* __restrict__ Wdtd,
                          const float* __restrict__ Wconv, const float* __restrict__ Wdiss) {
    int idx = blockIdx.x * 256 + threadIdx.x;          // 48*8192
    int row = idx >> 13, col = idx & 8191;
    float v;
    if (row < 4)        v = Wr[row * INDIM + col];
    else if (row < 8)   v = Ww[(row - 4) * INDIM + col];
    else if (row == 8)  v = Wdtc[col];
    else if (row == 9)  v = Wdtd[col];
    else if (row < 26)  v = Wconv[(row - 10) * INDIM + col];
    else if (row < 42)  v = Wdiss[(row - 26) * INDIM + col];
    else                v = 0.0f;
    g_Wcat[idx] = v;
}

// ---------------- prep: W_mod fp32 -> bf16 ----------------
__global__ void prep_wmod(const float* __restrict__ Wmod) {
    int i = blockIdx.x * 256 + threadIdx.x;            // over EMB*EMB/4 float4
    float4 v = reinterpret_cast<const float4*>(Wmod)[i];
    __nv_bfloat162 lo = __floats2bfloat162_rn(v.x, v.y);
    __nv_bfloat162 hi = __floats2bfloat162_rn(v.z, v.w);
    uint2 u;
    u.x = *reinterpret_cast<unsigned*>(&lo);
    u.y = *reinterpret_cast<unsigned*>(&hi);
    reinterpret_cast<uint2*>(g_wmodb)[i] = u;
}

// ---------------- phase A: 48 dots + sumsq per row ----------------
// grid (64, 4): 64 blocks of 128 rows, 4 j-quarters of 2048.
// Block 256 threads = 8 warps; warp w owns k = {w, w+8, ..., w+40};
// lane owns rows {lane, lane+32, lane+64, lane+96}.
__global__ void __launch_bounds__(256) k_dots(const float* __restrict__ x) {
    __shared__ float xs[64][129];   // [j within tile][row], pad 129 -> conflict-free reads
    __shared__ float ws[48][64];    // [k][j within tile]
    int t = threadIdx.x, lane = t & 31, wid = t >> 5;
    int rb = blockIdx.x;
    int jbase = blockIdx.y * 2048;

    float acc[4][6];
#pragma unroll
    for (int p = 0; p < 4; p++)
#pragma unroll
        for (int q = 0; q < 6; q++) acc[p][q] = 0.0f;
    float asq[4] = {0.0f, 0.0f, 0.0f, 0.0f};

    const float4* x4 = reinterpret_cast<const float4*>(x);
    const float4* w4 = reinterpret_cast<const float4*>(g_Wcat);

    for (int jt = 0; jt < 2048; jt += 64) {
        int jcol4 = (jbase + jt) >> 2;
        __syncthreads();
#pragma unroll
        for (int i = 0; i < 8; i++) {                  // x tile: 128 rows x 16 float4
            int idx = t + i * 256;
            int row = idx >> 4, c4 = idx & 15;
            float4 v = x4[(size_t)(rb * 128 + row) * 2048 + jcol4 + c4];
            xs[c4 * 4 + 0][row] = v.x;
            xs[c4 * 4 + 1][row] = v.y;
            xs[c4 * 4 + 2][row] = v.z;
            xs[c4 * 4 + 3][row] = v.w;
        }
#pragma unroll
        for (int i = 0; i < 3; i++) {                  // w tile: 48 rows x 16 float4
            int idx = t + i * 256;
            int row = idx >> 4, c4 = idx & 15;
            *reinterpret_cast<float4*>(&ws[row][c4 * 4]) = w4[row * 2048 + jcol4 + c4];
        }
        __syncthreads();
#pragma unroll 4
        for (int j4 = 0; j4 < 64; j4 += 4) {
            float xv[4][4];
#pragma unroll
            for (int jj = 0; jj < 4; jj++)
#pragma unroll
                for (int p = 0; p < 4; p++)
                    xv[p][jj] = xs[j4 + jj][lane + 32 * p];
#pragma unroll
            for (int q = 0; q < 6; q++) {
                float4 w = *reinterpret_cast<const float4*>(&ws[wid + 8 * q][j4]);
#pragma unroll
                for (int p = 0; p < 4; p++)
                    acc[p][q] += xv[p][0] * w.x + xv[p][1] * w.y + xv[p][2] * w.z + xv[p][3] * w.w;
            }
            if (wid == 0) {
#pragma unroll
                for (int p = 0; p < 4; p++)
                    asq[p] += xv[p][0] * xv[p][0] + xv[p][1] * xv[p][1]
                            + xv[p][2] * xv[p][2] + xv[p][3] * xv[p][3];
            }
        }
    }
#pragma unroll
    for (int p = 0; p < 4; p++) {
        int grow = rb * 128 + lane + 32 * p;
        float* dst = &g_dots[((size_t)blockIdx.y * BROWS + grow) * 52];
#pragma unroll
        for (int q = 0; q < 6; q++) dst[wid + 8 * q] = acc[p][q];
        if (wid == 0) dst[48] = asq[p];
    }
}

// ---------------- phase B: per-row 4x4 finalize (expm, rw, ww, c) ----------------
__device__ __forceinline__ float sigmoidf_(float z) { return 1.0f / (1.0f + expf(-z)); }

__global__ void k_finalize(const float* __restrict__ read_in, const float* __restrict__ alpha_ri,
                           const float* __restrict__ write_out, const float* __restrict__ alpha_wo,
                           const float* __restrict__ log_dt_c, const float* __restrict__ b_dtc,
                           const float* __restrict__ log_dt_d, const float* __restrict__ b_dtd,
                           const float* __restrict__ conserv_A, const float* __restrict__ b_conv,
                           const float* __restrict__ diss_A, const float* __restrict__ b_diss) {
    int row = blockIdx.x * 256 + threadIdx.x;
    if (row >= BROWS) return;
    float d[42];
    float sq = 0.0f;
#pragma unroll
    for (int k = 0; k < 42; k++) d[k] = 0.0f;
#pragma unroll
    for (int h = 0; h < 4; h++) {
        const float* p = &g_dots[((size_t)h * BROWS + row) * 52];
#pragma unroll
        for (int k = 0; k < 42; k++) d[k] += p[k];
        sq += p[48];
    }
    float invr = rsqrtf(sq * (1.0f / 8192.0f) + 1e-6f);

    float M[16], R[16];
#pragma unroll
    for (int i = 0; i < 16; i++) {
        M[i] = conserv_A[i] + d[10 + i] * invr + b_conv[i];
        R[i] = diss_A[i]    + d[26 + i] * invr + b_diss[i];
    }
    float dtc = 1e-3f + 0.999f * sigmoidf_(log_dt_c[0] + d[8] * invr + b_dtc[0]);
    float dtd = 1e-3f + 0.999f * sigmoidf_(log_dt_d[0] + d[9] * invr + b_dtd[0]);

    float A[16];
#pragma unroll
    for (int i = 0; i < 4; i++)
#pragma unroll
        for (int j = 0; j < 4; j++) {
            float kij = 0.0f;
#pragma unroll
            for (int l = 0; l < 4; l++) kij += R[i * 4 + l] * R[j * 4 + l];
            A[i * 4 + j] = dtc * (M[i * 4 + j] - M[j * 4 + i]) - dtd * kij;
        }

    // expm: scale 2^-4, order-8 Taylor, square 4x (matches reference)
    float As[16], E[16], T[16];
#pragma unroll
    for (int i = 0; i < 16; i++) { As[i] = A[i] * 0.0625f; T[i] = As[i]; }
#pragma unroll
    for (int i = 0; i < 16; i++) E[i] = ((i % 5 == 0) ? 1.0f : 0.0f) + As[i];
    const float rk[7] = {0.5f, 1.0f / 3.0f, 0.25f, 0.2f, 1.0f / 6.0f, 1.0f / 7.0f, 0.125f};
#pragma unroll
    for (int kk = 0; kk < 7; kk++) {
        float Tn[16];
#pragma unroll
        for (int i = 0; i < 4; i++)
#pragma unroll
            for (int j = 0; j < 4; j++) {
                float s = 0.0f;
#pragma unroll
                for (int l = 0; l < 4; l++) s += T[i * 4 + l] * As[l * 4 + j];
                Tn[i * 4 + j] = s * rk[kk];
            }
#pragma unroll
        for (int i = 0; i < 16; i++) { T[i] = Tn[i]; E[i] += Tn[i]; }
    }
#pragma unroll
    for (int s2 = 0; s2 < 4; s2++) {
        float En[16];
#pragma unroll
        for (int i = 0; i < 4; i++)
#pragma unroll
            for (int j = 0; j < 4; j++) {
                float s = 0.0f;
#pragma unroll
                for (int l = 0; l < 4; l++) s += E[i * 4 + l] * E[l * 4 + j];
                En[i * 4 + j] = s;
            }
#pragma unroll
        for (int i = 0; i < 16; i++) E[i] = En[i];
    }

    float rw[4], wwv[4];
#pragma unroll
    for (int n = 0; n < 4; n++) {
        rw[n]  = sigmoidf_(read_in[n] + alpha_ri[0] * d[n] * invr);
        wwv[n] = write_out[n] + alpha_wo[0] * d[4 + n] * invr;
    }
    float* pp = &g_params[(size_t)row * 24];
#pragma unroll
    for (int i = 0; i < 16; i++) pp[i] = E[i];
#pragma unroll
    for (int n = 0; n < 4; n++) pp[16 + n] = wwv[n];
#pragma unroll
    for (int j = 0; j < 4; j++) {
        float s = 0.0f;
#pragma unroll
        for (int n = 0; n < 4; n++) s += rw[n] * E[n * 4 + j];
        pp[20 + j] = s;           // c[j]
    }
}

// ---------------- branch[b,d] = sum_j c[j] * x[b,j,d]  (bf16 out) ----------------
__global__ void k_branch(const float* __restrict__ x) {
    int b = blockIdx.x;
    const float* pp = &g_params[(size_t)b * 24];
    float c0 = pp[20], c1 = pp[21], c2 = pp[22], c3 = pp[23];
    const float4* xr = reinterpret_cast<const float4*>(x) + (size_t)b * 2048;
#pragma unroll
    for (int it = 0; it < 2; it++) {
        int i = threadIdx.x + it * 256;
        float4 x0 = xr[i], x1 = xr[512 + i], x2 = xr[1024 + i], x3 = xr[1536 + i];
        float4 br;
        br.x = c0 * x0.x + c1 * x1.x + c2 * x2.x + c3 * x3.x;
        br.y = c0 * x0.y + c1 * x1.y + c2 * x2.y + c3 * x3.y;
        br.z = c0 * x0.z + c1 * x1.z + c2 * x2.z + c3 * x3.z;
        br.w = c0 * x0.w + c1 * x1.w + c2 * x2.w + c3 * x3.w;
        __nv_bfloat162 lo = __floats2bfloat162_rn(br.x, br.y);
        __nv_bfloat162 hi = __floats2bfloat162_rn(br.z, br.w);
        uint2 u;
        u.x = *reinterpret_cast<unsigned*>(&lo);
        u.y = *reinterpret_cast<unsigned*>(&hi);
        reinterpret_cast<uint2*>(g_branch)[(size_t)b * 512 + i] = u;
    }
}

// ---------------- y = branch @ W_mod^T (bf16 mma) fused with epilogue ----------------
__device__ __forceinline__ unsigned smem_u32_(const void* p) {
    return (unsigned)__cvta_generic_to_shared(p);
}

#define LDSM_X4(R0, R1, R2, R3, ADDR) \
    asm volatile("ldmatrix.sync.aligned.m8n8.x4.shared.b16 {%0,%1,%2,%3}, [%4];" \
                 : "=r"(R0), "=r"(R1), "=r"(R2), "=r"(R3) : "r"(ADDR))

#define MMA16816(C, A, B) \
    asm volatile("mma.sync.aligned.m16n8k16.row.col.f32.bf16.bf16.f32 " \
                 "{%0,%1,%2,%3}, {%4,%5,%6,%7}, {%8,%9}, {%0,%1,%2,%3};" \
                 : "+f"((C)[0]), "+f"((C)[1]), "+f"((C)[2]), "+f"((C)[3]) \
                 : "r"((A)[0]), "r"((A)[1]), "r"((A)[2]), "r"((A)[3]), \
                   "r"((B)[0]), "r"((B)[1]))

__global__ void __launch_bounds__(256) k_gemm_epi(const float* __restrict__ x,
                                                  float* __restrict__ out) {
    __shared__ __align__(16) __nv_bfloat16 Asm[128][40];
    __shared__ __align__(16) __nv_bfloat16 Bsm[128][40];
    __shared__ float Ps[128][20];
    int t = threadIdx.x, lane = t & 31, wid = t >> 5;
    int warp_m = wid >> 2, warp_n = wid & 3;
    int brow0 = blockIdx.y * 128, ncol0 = blockIdx.x * 128;

    for (int i = t; i < 128 * 20; i += 256)
        Ps[i / 20][i % 20] = g_params[(size_t)(brow0 + i / 20) * 24 + (i % 20)];

    float acc[4][4][4];
#pragma unroll
    for (int mf = 0; mf < 4; mf++)
#pragma unroll
        for (int nf = 0; nf < 4; nf++)
#pragma unroll
            for (int e = 0; e < 4; e++) acc[mf][nf][e] = 0.0f;

    int r_ld = t >> 2, cg = (t & 3) * 8;

    for (int kt = 0; kt < 2048; kt += 32) {
        __syncthreads();
        *reinterpret_cast<uint4*>(&Asm[r_ld][cg]) =
            *reinterpret_cast<const uint4*>(&g_branch[(size_t)(brow0 + r_ld) * 2048 + kt + cg]);
        *reinterpret_cast<uint4*>(&Asm[r_ld + 64][cg]) =
            *reinterpret_cast<const uint4*>(&g_branch[(size_t)(brow0 + r_ld + 64) * 2048 + kt + cg]);
        *reinterpret_cast<uint4*>(&Bsm[r_ld][cg]) =
            *reinterpret_cast<const uint4*>(&g_wmodb[(size_t)(ncol0 + r_ld) * 2048 + kt + cg]);
        *reinterpret_cast<uint4*>(&Bsm[r_ld + 64][cg]) =
            *reinterpret_cast<const uint4*>(&g_wmodb[(size_t)(ncol0 + r_ld + 64) * 2048 + kt + cg]);
        __syncthreads();
#pragma unroll
        for (int ks = 0; ks < 2; ks++) {
            unsigned a[4][4], b[4][2];
#pragma unroll
            for (int mf = 0; mf < 4; mf++) {
                int row = warp_m * 64 + mf * 16 + (lane & 15);
                int col = ks * 16 + (lane >> 4) * 8;
                unsigned addr = smem_u32_(&Asm[row][col]);
                LDSM_X4(a[mf][0], a[mf][1], a[mf][2], a[mf][3], addr);
            }
#pragma unroll
            for (int nfp = 0; nfp < 2; nfp++) {
                int row = warp_n * 32 + nfp * 16 + ((lane >> 4) << 3) + (lane & 7);
                int col = ks * 16 + ((lane >> 3) & 1) * 8;
                unsigned addr = smem_u32_(&Bsm[row][col]);
                LDSM_X4(b[2 * nfp][0], b[2 * nfp][1], b[2 * nfp + 1][0], b[2 * nfp + 1][1], addr);
            }
#pragma unroll
            for (int mf = 0; mf < 4; mf++)
#pragma unroll
                for (int nf = 0; nf < 4; nf++)
                    MMA16816(acc[mf][nf], a[mf], b[nf]);
        }
    }

    // fused epilogue: out[b, n, d] = sum_j E[n][j]*x[b, j, d] + ww[n]*y[b, d]
#pragma unroll
    for (int mf = 0; mf < 4; mf++) {
#pragma unroll
        for (int nf = 0; nf < 4; nf++) {
            int rbase = warp_m * 64 + mf * 16 + (lane >> 2);
            int cbase = warp_n * 32 + nf * 8 + 2 * (lane & 3);
#pragma unroll
            for (int half = 0; half < 2; half++) {
                int r = rbase + 8 * half;
                size_t b = (size_t)(brow0 + r);
                int dd = ncol0 + cbase;
                float y0 = acc[mf][nf][2 * half];
                float y1 = acc[mf][nf][2 * half + 1];
                const float* pr = Ps[r];
                const float* xb = x + b * 8192 + dd;
                float2 xv[4];
#pragma unroll
                for (int j = 0; j < 4; j++)
                    xv[j] = *reinterpret_cast<const float2*>(xb + j * 2048);
                float* ob = out + b * 8192 + dd;
#pragma unroll
                for (int n = 0; n < 4; n++) {
                    float m0 = pr[n * 4 + 0] * xv[0].x + pr[n * 4 + 1] * xv[1].x
                             + pr[n * 4 + 2] * xv[2].x + pr[n * 4 + 3] * xv[3].x;
                    float m1 = pr[n * 4 + 0] * xv[0].y + pr[n * 4 + 1] * xv[1].y
                             + pr[n * 4 + 2] * xv[2].y + pr[n * 4 + 3] * xv[3].y;
                    float w = pr[16 + n];
                    float2 o;
                    o.x = m0 + w * y0;
                    o.y = m1 + w * y1;
                    *reinterpret_cast<float2*>(ob + n * 2048) = o;
                }
            }
        }
    }
}

// ---------------- launch ----------------
extern "C" void kernel_launch(void* const* d_in, const int* in_sizes, int n_in,
                              void* d_out, int out_size) {
    const float* x          = (const float*)d_in[0];
    const float* read_in    = (const float*)d_in[1];
    const float* alpha_ri   = (const float*)d_in[2];
    const float* write_out  = (const float*)d_in[3];
    const float* alpha_wo   = (const float*)d_in[4];
    const float* W_read     = (const float*)d_in[5];
    const float* W_write    = (const float*)d_in[6];
    const float* log_dt_c   = (const float*)d_in[7];
    const float* log_dt_d   = (const float*)d_in[8];
    const float* W_dtc      = (const float*)d_in[9];
    const float* b_dtc      = (const float*)d_in[10];
    const float* W_dtd      = (const float*)d_in[11];
    const float* b_dtd      = (const float*)d_in[12];
    const float* conserv_A  = (const float*)d_in[13];
    const float* W_conv     = (const float*)d_in[14];
    const float* b_conv     = (const float*)d_in[15];
    const float* diss_A     = (const float*)d_in[16];
    const float* W_diss     = (const float*)d_in[17];
    const float* b_diss     = (const float*)d_in[18];
    const float* W_mod      = (const float*)d_in[19];
    float* out = (float*)d_out;

    prep_wcat<<<1536, 256>>>(W_read, W_write, W_dtc, W_dtd, W_conv, W_diss);
    prep_wmod<<<4096, 256>>>(W_mod);
    k_dots<<<dim3(64, 4), 256>>>(x);
    k_finalize<<<32, 256>>>(read_in, alpha_ri, write_out, alpha_wo,
                            log_dt_c, b_dtc, log_dt_d, b_dtd,
                            conserv_A, b_conv, diss_A, b_diss);
    k_branch<<<8192, 256>>>(x);
    k_gemm_epi<<<dim3(16, 64), 256>>>(x, out);
}

// round 9
// speedup vs baseline: 1.7689x; 1.7689x over previous
#include <cuda_runtime.h>
#include <cuda_bf16.h>
#include <cstdint>
#include <cstddef>

#define BROWS 8192
#define INDIM 8192
#define EMBD  2048

// ---------------- device scratch (static; no allocs) ----------------
__device__ __nv_bfloat16  g_Wcath[48 * INDIM];        // packed projection weights, bf16 hi
__device__ __nv_bfloat16  g_Wcatl[48 * INDIM];        // bf16 lo (residual)
__device__ float          g_dots[4 * 52 * BROWS];     // transposed: [quarter][k][row]; k=48 -> sum(x^2)
__device__ float          g_params[BROWS * 24];       // per row: E[16], ww[4], c[4]
__device__ __nv_bfloat16  g_branch[BROWS * EMBD];
__device__ __nv_bfloat16  g_wmodb[EMBD * EMBD];

// ---------------- helpers ----------------
__device__ __forceinline__ unsigned smem_u32_(const void* p) {
    return (unsigned)__cvta_generic_to_shared(p);
}
#define LDSM_X4(R0, R1, R2, R3, ADDR) \
    asm volatile("ldmatrix.sync.aligned.m8n8.x4.shared.b16 {%0,%1,%2,%3}, [%4];" \
                 : "=r"(R0), "=r"(R1), "=r"(R2), "=r"(R3) : "r"(ADDR))
#define MMA16816(C, A, B) \
    asm volatile("mma.sync.aligned.m16n8k16.row.col.f32.bf16.bf16.f32 " \
                 "{%0,%1,%2,%3}, {%4,%5,%6,%7}, {%8,%9}, {%0,%1,%2,%3};" \
                 : "+f"((C)[0]), "+f"((C)[1]), "+f"((C)[2]), "+f"((C)[3]) \
                 : "r"((A)[0]), "r"((A)[1]), "r"((A)[2]), "r"((A)[3]), \
                   "r"((B)[0]), "r"((B)[1]))
#define CP_ASYNC16(SM, GM) \
    asm volatile("cp.async.cg.shared.global [%0], [%1], 16;" :: "r"(SM), "l"(GM))
#define CP_COMMIT() asm volatile("cp.async.commit_group;" ::)
#define CP_WAIT(N)  asm volatile("cp.async.wait_group %0;" :: "n"(N))

__device__ __forceinline__ unsigned pack_bf16x2_(float a, float b) {
    __nv_bfloat162 v = __floats2bfloat162_rn(a, b);
    return *reinterpret_cast<unsigned*>(&v);
}

// ---------------- prep: pack 48 projection rows -> bf16 hi/lo ----------------
__global__ void prep_wcatb(const float* __restrict__ Wr, const float* __restrict__ Ww,
                           const float* __restrict__ Wdtc, const float* __restrict__ Wdtd,
                           const float* __restrict__ Wconv, const float* __restrict__ Wdiss) {
    int idx = blockIdx.x * 256 + threadIdx.x;          // 48*8192
    int row = idx >> 13, col = idx & 8191;
    float v;
    if (row < 4)        v = Wr[row * INDIM + col];
    else if (row < 8)   v = Ww[(row - 4) * INDIM + col];
    else if (row == 8)  v = Wdtc[col];
    else if (row == 9)  v = Wdtd[col];
    else if (row < 26)  v = Wconv[(row - 10) * INDIM + col];
    else if (row < 42)  v = Wdiss[(row - 26) * INDIM + col];
    else                v = 0.0f;
    __nv_bfloat16 h = __float2bfloat16(v);
    g_Wcath[idx] = h;
    g_Wcatl[idx] = __float2bfloat16(v - __bfloat162float(h));
}

// ---------------- prep: W_mod fp32 -> bf16 ----------------
__global__ void prep_wmod(const float* __restrict__ Wmod) {
    int i = blockIdx.x * 256 + threadIdx.x;            // over EMB*EMB/4 float4
    float4 v = reinterpret_cast<const float4*>(Wmod)[i];
    uint2 u;
    u.x = pack_bf16x2_(v.x, v.y);
    u.y = pack_bf16x2_(v.z, v.w);
    reinterpret_cast<uint2*>(g_wmodb)[i] = u;
}

// ---------------- phase A: 48 dots + sumsq, via compensated bf16 MMA ----------------
// grid (64, 4): 64 blocks of 128 rows, 4 j-quarters of 2048. 256 threads = 8 warps.
// dot = xh*wh + xh*wl + xl*wh  (lo*lo dropped; residual ~1.6e-5 relative)
__global__ void __launch_bounds__(256) k_dots_tc(const float* __restrict__ x) {
    __shared__ __align__(16) __nv_bfloat16 Ah[128][72];
    __shared__ __align__(16) __nv_bfloat16 Al[128][72];
    __shared__ __align__(16) __nv_bfloat16 Bh[48][72];
    __shared__ __align__(16) __nv_bfloat16 Bl[48][72];
    int t = threadIdx.x, lane = t & 31, wid = t >> 5;
    int rb = blockIdx.x;
    int h = blockIdx.y;
    int jbase = h * 2048;

    float acc[6][4];
#pragma unroll
    for (int q = 0; q < 6; q++)
#pragma unroll
        for (int e = 0; e < 4; e++) acc[q][e] = 0.0f;
    float sq[8];
#pragma unroll
    for (int i = 0; i < 8; i++) sq[i] = 0.0f;

    const float4* x4 = reinterpret_cast<const float4*>(x);

    for (int jt = 0; jt < 2048; jt += 64) {
        __syncthreads();
        int jcol4 = (jbase + jt) >> 2;
        int c4 = t & 15;
#pragma unroll
        for (int i = 0; i < 8; i++) {                  // x tile: 128 rows x 16 float4 -> hi/lo bf16
            int row = (t >> 4) + 16 * i;
            float4 v = x4[(size_t)(rb * 128 + row) * 2048 + jcol4 + c4];
            sq[i] += v.x * v.x + v.y * v.y + v.z * v.z + v.w * v.w;
            __nv_bfloat162 hx = __floats2bfloat162_rn(v.x, v.y);
            __nv_bfloat162 hz = __floats2bfloat162_rn(v.z, v.w);
            float2 hxf = __bfloat1622float2(hx);
            float2 hzf = __bfloat1622float2(hz);
            uint2 uh, ul;
            uh.x = *reinterpret_cast<unsigned*>(&hx);
            uh.y = *reinterpret_cast<unsigned*>(&hz);
            ul.x = pack_bf16x2_(v.x - hxf.x, v.y - hxf.y);
            ul.y = pack_bf16x2_(v.z - hzf.x, v.w - hzf.y);
            *reinterpret_cast<uint2*>(&Ah[row][c4 * 4]) = uh;
            *reinterpret_cast<uint2*>(&Al[row][c4 * 4]) = ul;
        }
#pragma unroll
        for (int i = 0; i < 3; i++) {                  // w tiles: 48 rows x 64 bf16, hi + lo
            int idx = t + i * 256;
            int row = idx >> 4, cc = idx & 15;
            size_t goff = (size_t)row * 8192 + jbase + jt + cc * 4;
            *reinterpret_cast<uint2*>(&Bh[row][cc * 4]) =
                *reinterpret_cast<const uint2*>(&g_Wcath[goff]);
            *reinterpret_cast<uint2*>(&Bl[row][cc * 4]) =
                *reinterpret_cast<const uint2*>(&g_Wcatl[goff]);
        }
        __syncthreads();
#pragma unroll
        for (int ks = 0; ks < 4; ks++) {
            unsigned ah[4], al[4], bh[6][2], bl[6][2];
            {
                int row = wid * 16 + (lane & 15);
                int col = ks * 16 + (lane >> 4) * 8;
                LDSM_X4(ah[0], ah[1], ah[2], ah[3], smem_u32_(&Ah[row][col]));
                LDSM_X4(al[0], al[1], al[2], al[3], smem_u32_(&Al[row][col]));
            }
#pragma unroll
            for (int nb = 0; nb < 3; nb++) {
                int row = nb * 16 + ((lane >> 4) << 3) + (lane & 7);
                int col = ks * 16 + ((lane >> 3) & 1) * 8;
                LDSM_X4(bh[2 * nb][0], bh[2 * nb][1], bh[2 * nb + 1][0], bh[2 * nb + 1][1],
                        smem_u32_(&Bh[row][col]));
                LDSM_X4(bl[2 * nb][0], bl[2 * nb][1], bl[2 * nb + 1][0], bl[2 * nb + 1][1],
                        smem_u32_(&Bl[row][col]));
            }
#pragma unroll
            for (int q = 0; q < 6; q++) {
                MMA16816(acc[q], ah, bh[q]);
                MMA16816(acc[q], ah, bl[q]);
                MMA16816(acc[q], al, bh[q]);
            }
        }
    }

    // write dots (transposed layout [h][k][row])
#pragma unroll
    for (int q = 0; q < 6; q++) {
        int row0 = rb * 128 + wid * 16 + (lane >> 2);
        int col0 = q * 8 + (lane & 3) * 2;
        size_t base = (size_t)h * 52 * BROWS;
        g_dots[base + (size_t)(col0    ) * BROWS + row0    ] = acc[q][0];
        g_dots[base + (size_t)(col0 + 1) * BROWS + row0    ] = acc[q][1];
        g_dots[base + (size_t)(col0    ) * BROWS + row0 + 8] = acc[q][2];
        g_dots[base + (size_t)(col0 + 1) * BROWS + row0 + 8] = acc[q][3];
    }
    // sumsq: reduce across the 16 threads sharing each row (fp32 exact)
#pragma unroll
    for (int i = 0; i < 8; i++) {
        float v = sq[i];
        v += __shfl_xor_sync(0xffffffffu, v, 1);
        v += __shfl_xor_sync(0xffffffffu, v, 2);
        v += __shfl_xor_sync(0xffffffffu, v, 4);
        v += __shfl_xor_sync(0xffffffffu, v, 8);
        if ((t & 15) == 0) {
            int row = rb * 128 + (t >> 4) + 16 * i;
            g_dots[((size_t)h * 52 + 48) * BROWS + row] = v;
        }
    }
}

// ---------------- phase B: per-row 4x4 finalize (expm, rw, ww, c) ----------------
__device__ __forceinline__ float sigmoidf_(float z) { return 1.0f / (1.0f + expf(-z)); }

__global__ void k_finalize(const float* __restrict__ read_in, const float* __restrict__ alpha_ri,
                           const float* __restrict__ write_out, const float* __restrict__ alpha_wo,
                           const float* __restrict__ log_dt_c, const float* __restrict__ b_dtc,
                           const float* __restrict__ log_dt_d, const float* __restrict__ b_dtd,
                           const float* __restrict__ conserv_A, const float* __restrict__ b_conv,
                           const float* __restrict__ diss_A, const float* __restrict__ b_diss) {
    int row = blockIdx.x * 256 + threadIdx.x;
    if (row >= BROWS) return;
    float d[42];
    float sq = 0.0f;
#pragma unroll
    for (int k = 0; k < 42; k++) d[k] = 0.0f;
#pragma unroll
    for (int h = 0; h < 4; h++) {
        size_t base = (size_t)h * 52 * BROWS + row;
#pragma unroll
        for (int k = 0; k < 42; k++) d[k] += g_dots[base + (size_t)k * BROWS];
        sq += g_dots[base + (size_t)48 * BROWS];
    }
    float invr = rsqrtf(sq * (1.0f / 8192.0f) + 1e-6f);

    float M[16], R[16];
#pragma unroll
    for (int i = 0; i < 16; i++) {
        M[i] = conserv_A[i] + d[10 + i] * invr + b_conv[i];
        R[i] = diss_A[i]    + d[26 + i] * invr + b_diss[i];
    }
    float dtc = 1e-3f + 0.999f * sigmoidf_(log_dt_c[0] + d[8] * invr + b_dtc[0]);
    float dtd = 1e-3f + 0.999f * sigmoidf_(log_dt_d[0] + d[9] * invr + b_dtd[0]);

    float A[16];
#pragma unroll
    for (int i = 0; i < 4; i++)
#pragma unroll
        for (int j = 0; j < 4; j++) {
            float kij = 0.0f;
#pragma unroll
            for (int l = 0; l < 4; l++) kij += R[i * 4 + l] * R[j * 4 + l];
            A[i * 4 + j] = dtc * (M[i * 4 + j] - M[j * 4 + i]) - dtd * kij;
        }

    // expm: scale 2^-4, order-8 Taylor, square 4x (matches reference)
    float As[16], E[16], T[16];
#pragma unroll
    for (int i = 0; i < 16; i++) { As[i] = A[i] * 0.0625f; T[i] = As[i]; }
#pragma unroll
    for (int i = 0; i < 16; i++) E[i] = ((i % 5 == 0) ? 1.0f : 0.0f) + As[i];
    const float rk[7] = {0.5f, 1.0f / 3.0f, 0.25f, 0.2f, 1.0f / 6.0f, 1.0f / 7.0f, 0.125f};
#pragma unroll
    for (int kk = 0; kk < 7; kk++) {
        float Tn[16];
#pragma unroll
        for (int i = 0; i < 4; i++)
#pragma unroll
            for (int j = 0; j < 4; j++) {
                float s = 0.0f;
#pragma unroll
                for (int l = 0; l < 4; l++) s += T[i * 4 + l] * As[l * 4 + j];
                Tn[i * 4 + j] = s * rk[kk];
            }
#pragma unroll
        for (int i = 0; i < 16; i++) { T[i] = Tn[i]; E[i] += Tn[i]; }
    }
#pragma unroll
    for (int s2 = 0; s2 < 4; s2++) {
        float En[16];
#pragma unroll
        for (int i = 0; i < 4; i++)
#pragma unroll
            for (int j = 0; j < 4; j++) {
                float s = 0.0f;
#pragma unroll
                for (int l = 0; l < 4; l++) s += E[i * 4 + l] * E[l * 4 + j];
                En[i * 4 + j] = s;
            }
#pragma unroll
        for (int i = 0; i < 16; i++) E[i] = En[i];
    }

    float rw[4], wwv[4];
#pragma unroll
    for (int n = 0; n < 4; n++) {
        rw[n]  = sigmoidf_(read_in[n] + alpha_ri[0] * d[n] * invr);
        wwv[n] = write_out[n] + alpha_wo[0] * d[4 + n] * invr;
    }
    float* pp = &g_params[(size_t)row * 24];
#pragma unroll
    for (int i = 0; i < 16; i++) pp[i] = E[i];
#pragma unroll
    for (int n = 0; n < 4; n++) pp[16 + n] = wwv[n];
#pragma unroll
    for (int j = 0; j < 4; j++) {
        float s = 0.0f;
#pragma unroll
        for (int n = 0; n < 4; n++) s += rw[n] * E[n * 4 + j];
        pp[20 + j] = s;           // c[j]
    }
}

// ---------------- branch[b,d] = sum_j c[j] * x[b,j,d]  (bf16 out) ----------------
__global__ void k_branch(const float* __restrict__ x) {
    int b = blockIdx.x;
    const float* pp = &g_params[(size_t)b * 24];
    float c0 = pp[20], c1 = pp[21], c2 = pp[22], c3 = pp[23];
    const float4* xr = reinterpret_cast<const float4*>(x) + (size_t)b * 2048;
#pragma unroll
    for (int it = 0; it < 2; it++) {
        int i = threadIdx.x + it * 256;
        float4 x0 = xr[i], x1 = xr[512 + i], x2 = xr[1024 + i], x3 = xr[1536 + i];
        float4 br;
        br.x = c0 * x0.x + c1 * x1.x + c2 * x2.x + c3 * x3.x;
        br.y = c0 * x0.y + c1 * x1.y + c2 * x2.y + c3 * x3.y;
        br.z = c0 * x0.z + c1 * x1.z + c2 * x2.z + c3 * x3.z;
        br.w = c0 * x0.w + c1 * x1.w + c2 * x2.w + c3 * x3.w;
        uint2 u;
        u.x = pack_bf16x2_(br.x, br.y);
        u.y = pack_bf16x2_(br.z, br.w);
        reinterpret_cast<uint2*>(g_branch)[(size_t)b * 512 + i] = u;
    }
}

// ---------------- y = branch @ W_mod^T (bf16 mma, cp.async double-buffered) ----------------
// Dynamic smem: A[2][128][72] bf16, B[2][128][72] bf16, Ps[128][20] fp32.
__global__ void __launch_bounds__(256, 2) k_gemm_epi(const float* __restrict__ x,
                                                     float* __restrict__ out) {
    extern __shared__ __align__(16) char dynsm[];
    __nv_bfloat16 (*Asm)[72] = reinterpret_cast<__nv_bfloat16(*)[72]>(dynsm);
    __nv_bfloat16 (*Bsm)[72] = reinterpret_cast<__nv_bfloat16(*)[72]>(dynsm + 2 * 128 * 72 * 2);
    float (*Ps)[20] = reinterpret_cast<float(*)[20]>(dynsm + 4 * 128 * 72 * 2);

    int t = threadIdx.x, lane = t & 31, wid = t >> 5;
    int warp_m = wid >> 2, warp_n = wid & 3;
    int brow0 = blockIdx.y * 128, ncol0 = blockIdx.x * 128;

    int r_ld = t >> 3, c8 = (t & 7) * 8;   // per-thread 16B chunk: 4 chunks cover 128x64

    // issue stage 0
    {
#pragma unroll
        for (int i = 0; i < 4; i++) {
            int row = r_ld + i * 32;
            CP_ASYNC16(smem_u32_(&Asm[row][c8]),
                       &g_branch[(size_t)(brow0 + row) * 2048 + c8]);
            CP_ASYNC16(smem_u32_(&Bsm[row][c8]),
                       &g_wmodb[(size_t)(ncol0 + row) * 2048 + c8]);
        }
        CP_COMMIT();
    }

    for (int i = t; i < 128 * 20; i += 256)
        Ps[i / 20][i % 20] = g_params[(size_t)(brow0 + i / 20) * 24 + (i % 20)];

    float acc[4][4][4];
#pragma unroll
    for (int mf = 0; mf < 4; mf++)
#pragma unroll
        for (int nf = 0; nf < 4; nf++)
#pragma unroll
            for (int e = 0; e < 4; e++) acc[mf][nf][e] = 0.0f;

#pragma unroll 1
    for (int it = 0; it < 32; it++) {
        if (it + 1 < 32) {
            int s = (it + 1) & 1;
            int kt = (it + 1) * 64;
#pragma unroll
            for (int i = 0; i < 4; i++) {
                int row = r_ld + i * 32;
                CP_ASYNC16(smem_u32_(&Asm[s * 128 + row][c8]),
                           &g_branch[(size_t)(brow0 + row) * 2048 + kt + c8]);
                CP_ASYNC16(smem_u32_(&Bsm[s * 128 + row][c8]),
                           &g_wmodb[(size_t)(ncol0 + row) * 2048 + kt + c8]);
            }
            CP_COMMIT();
            CP_WAIT(1);
        } else {
            CP_WAIT(0);
        }
        __syncthreads();
        int sb = (it & 1) * 128;
#pragma unroll
        for (int ks = 0; ks < 4; ks++) {
            unsigned a[4][4], b[4][2];
#pragma unroll
            for (int mf = 0; mf < 4; mf++) {
                int row = sb + warp_m * 64 + mf * 16 + (lane & 15);
                int col = ks * 16 + (lane >> 4) * 8;
                LDSM_X4(a[mf][0], a[mf][1], a[mf][2], a[mf][3], smem_u32_(&Asm[row][col]));
            }
#pragma unroll
            for (int nfp = 0; nfp < 2; nfp++) {
                int row = sb + warp_n * 32 + nfp * 16 + ((lane >> 4) << 3) + (lane & 7);
                int col = ks * 16 + ((lane >> 3) & 1) * 8;
                LDSM_X4(b[2 * nfp][0], b[2 * nfp][1], b[2 * nfp + 1][0], b[2 * nfp + 1][1],
                        smem_u32_(&Bsm[row][col]));
            }
#pragma unroll
            for (int mf = 0; mf < 4; mf++)
#pragma unroll
                for (int nf = 0; nf < 4; nf++)
                    MMA16816(acc[mf][nf], a[mf], b[nf]);
        }
        __syncthreads();
    }

    // fused epilogue: out[b, n, d] = sum_j E[n][j]*x[b, j, d] + ww[n]*y[b, d]
#pragma unroll
    for (int mf = 0; mf < 4; mf++) {
#pragma unroll
        for (int nf = 0; nf < 4; nf++) {
            int rbase = warp_m * 64 + mf * 16 + (lane >> 2);
            int cbase = warp_n * 32 + nf * 8 + 2 * (lane & 3);
#pragma unroll
            for (int half = 0; half < 2; half++) {
                int r = rbase + 8 * half;
                size_t b = (size_t)(brow0 + r);
                int dd = ncol0 + cbase;
                float y0 = acc[mf][nf][2 * half];
                float y1 = acc[mf][nf][2 * half + 1];
                const float* pr = Ps[r];
                const float* xb = x + b * 8192 + dd;
                float2 xv[4];
#pragma unroll
                for (int j = 0; j < 4; j++)
                    xv[j] = *reinterpret_cast<const float2*>(xb + j * 2048);
                float* ob = out + b * 8192 + dd;
#pragma unroll
                for (int n = 0; n < 4; n++) {
                    float m0 = pr[n * 4 + 0] * xv[0].x + pr[n * 4 + 1] * xv[1].x
                             + pr[n * 4 + 2] * xv[2].x + pr[n * 4 + 3] * xv[3].x;
                    float m1 = pr[n * 4 + 0] * xv[0].y + pr[n * 4 + 1] * xv[1].y
                             + pr[n * 4 + 2] * xv[2].y + pr[n * 4 + 3] * xv[3].y;
                    float w = pr[16 + n];
                    float2 o;
                    o.x = m0 + w * y0;
                    o.y = m1 + w * y1;
                    *reinterpret_cast<float2*>(ob + n * 2048) = o;
                }
            }
        }
    }
}

// ---------------- launch ----------------
extern "C" void kernel_launch(void* const* d_in, const int* in_sizes, int n_in,
                              void* d_out, int out_size) {
    const float* x          = (const float*)d_in[0];
    const float* read_in    = (const float*)d_in[1];
    const float* alpha_ri   = (const float*)d_in[2];
    const float* write_out  = (const float*)d_in[3];
    const float* alpha_wo   = (const float*)d_in[4];
    const float* W_read     = (const float*)d_in[5];
    const float* W_write    = (const float*)d_in[6];
    const float* log_dt_c   = (const float*)d_in[7];
    const float* log_dt_d   = (const float*)d_in[8];
    const float* W_dtc      = (const float*)d_in[9];
    const float* b_dtc      = (const float*)d_in[10];
    const float* W_dtd      = (const float*)d_in[11];
    const float* b_dtd      = (const float*)d_in[12];
    const float* conserv_A  = (const float*)d_in[13];
    const float* W_conv     = (const float*)d_in[14];
    const float* b_conv     = (const float*)d_in[15];
    const float* diss_A     = (const float*)d_in[16];
    const float* W_diss     = (const float*)d_in[17];
    const float* b_diss     = (const float*)d_in[18];
    const float* W_mod      = (const float*)d_in[19];
    float* out = (float*)d_out;

    static int smem_set = 0;
    const int GEMM_SMEM = 4 * 128 * 72 * 2 + 128 * 20 * 4;   // 83968
    if (!smem_set) {
        cudaFuncSetAttribute(k_gemm_epi, cudaFuncAttributeMaxDynamicSharedMemorySize, GEMM_SMEM);
        smem_set = 1;
    }

    prep_wcatb<<<1536, 256>>>(W_read, W_write, W_dtc, W_dtd, W_conv, W_diss);
    prep_wmod<<<4096, 256>>>(W_mod);
    k_dots_tc<<<dim3(64, 4), 256>>>(x);
    k_finalize<<<32, 256>>>(read_in, alpha_ri, write_out, alpha_wo,
                            log_dt_c, b_dtc, log_dt_d, b_dtd,
                            conserv_A, b_conv, diss_A, b_diss);
    k_branch<<<8192, 256>>>(x);
    k_gemm_epi<<<dim3(16, 64), 256, GEMM_SMEM>>>(x, out);
}